// round 10
// baseline (speedup 1.0000x reference)
#include <cuda_runtime.h>
#include <cstdint>

#define PSZ 16
#define HW 224
#define NP 14          // patches per spatial dim (224/16)
#define S4 56          // float4 per strip row (gmem)
#define SS 57          // padded smem row stride (float4) -> conflict-free STS
#define ROW_BYTES 896  // 224 floats per strip row

__global__ __launch_bounds__(224, 8) void patch_rotate_kernel(
    const float* __restrict__ x,
    const void* __restrict__ mask_raw,
    float* __restrict__ out)
{
    __shared__ float4 tile[PSZ * SS];      // 16 x 57 float4 = 14592 B (linear output image, padded)

    const int bid = blockIdx.x;
    const int hi  = bid % NP;              // patch-row index
    const int bc  = bid / NP;              // b*3 + c
    const int b   = bc / 3;
    const int t   = threadIdx.x;           // 0..223
    const int lane = t & 31;

    // thread -> (patch, 4x4 sub-block): 16 consecutive lanes own one patch
    const int wi = t >> 4;                 // 0..13 patch column
    const int R  = (t >> 2) & 3;           // sub-block row group (rows 4R..4R+3)
    const int J  = t & 3;                  // sub-block fcol within patch
    const int fcol = 4 * wi + J;

    const size_t strip_f = (size_t)bc * (HW * HW) + (size_t)hi * (PSZ * HW);
    const float4* src4 = (const float4*)(x + strip_f);

    // ---- coalesced LDG.128 loads (R7-proven pattern: 4 x 128B lines per warp per k) ----
    float4 v[4];
    #pragma unroll
    for (int k = 0; k < 4; k++)
        v[k] = src4[(4*R + k) * S4 + fcol];

    // dtype probe: int32 bool -> every word 0/1; uint8 -> word>1 w.p. 7/8. P(miss)=8^-32.
    const unsigned pv = ((const unsigned int*)mask_raw)[lane];
    const int midx = b * (NP*NP) + wi * NP + hi;                      // mask[b, wi, hi]
    const unsigned char m8 = ((const unsigned char*)mask_raw)[midx];  // in-bounds either way

    const bool is_int32 = (__ballot_sync(0xFFFFFFFFu, pv > 1u) == 0u);
    bool mm;
    if (is_int32) mm = (((const int*)mask_raw)[midx] != 0);  // predicated: no OOB if uint8
    else          mm = (m8 != 0);

    // ---- assemble output strip image in smem: 4 STS.128 per thread, no LDS ----
    if (mm) {
        // in[4R+k][4J+e] -> out[4J+e][4R+k]: column vectors of v go to rows 4J+e, fcol 4wi+R
        const int cc = 4*wi + R;
        float4 w0 = make_float4(v[0].x, v[1].x, v[2].x, v[3].x);
        float4 w1 = make_float4(v[0].y, v[1].y, v[2].y, v[3].y);
        float4 w2 = make_float4(v[0].z, v[1].z, v[2].z, v[3].z);
        float4 w3 = make_float4(v[0].w, v[1].w, v[2].w, v[3].w);
        if (J & 2) {   // static order rotation: removes J<->J+2 bank collision
            tile[(4*J + 2) * SS + cc] = w2;
            tile[(4*J + 3) * SS + cc] = w3;
            tile[(4*J + 0) * SS + cc] = w0;
            tile[(4*J + 1) * SS + cc] = w1;
        } else {
            tile[(4*J + 0) * SS + cc] = w0;
            tile[(4*J + 1) * SS + cc] = w1;
            tile[(4*J + 2) * SS + cc] = w2;
            tile[(4*J + 3) * SS + cc] = w3;
        }
    } else {
        #pragma unroll
        for (int k = 0; k < 4; k++)
            tile[(4*R + k) * SS + fcol] = v[k];
    }

    // make generic-proxy STS visible to the async proxy, then sync the block
    asm volatile("fence.proxy.async.shared::cta;" ::: "memory");
    __syncthreads();

    // ---- one sequential 14KB burst: 16 x cp.async.bulk (896B, consecutive gmem rows) ----
    if (t == 0) {
        uint32_t sbase;
        asm("{ .reg .u64 tmp; cvta.to.shared.u64 tmp, %1; cvt.u32.u64 %0, tmp; }"
            : "=r"(sbase) : "l"(tile));
        const char* gdst = (const char*)(out + strip_f);
        #pragma unroll
        for (int i = 0; i < PSZ; i++) {
            asm volatile(
                "cp.async.bulk.global.shared::cta.bulk_group [%0], [%1], %2;"
                :: "l"(gdst + i * ROW_BYTES),
                   "r"(sbase + i * (SS * 16)),
                   "n"(ROW_BYTES)
                : "memory");
        }
        asm volatile("cp.async.bulk.commit_group;" ::: "memory");
        asm volatile("cp.async.bulk.wait_group 0;" ::: "memory");
    }
}

extern "C" void kernel_launch(void* const* d_in, const int* in_sizes, int n_in,
                              void* d_out, int out_size)
{
    const float* x    = (const float*)d_in[0];
    const void*  mask = d_in[1];
    float*       out  = (float*)d_out;

    // one block per (b, c, patch-row) strip = 256*3*14 = 10752 blocks
    patch_rotate_kernel<<<10752, 224>>>(x, mask, out);
}

// round 12
// speedup vs baseline: 1.0006x; 1.0006x over previous
#include <cuda_runtime.h>

#define PSZ 16
#define HW 224
#define NP 14          // patches per spatial dim (224/16)
#define S4 56          // float4 per strip row
#define PROWS 5        // padded smem row stride per patch (float4 units)
#define PSTRIDE 80     // per-patch smem size: 16 rows * 5 (float4)
#define STRIP4 896     // float4 per strip (16*56)

__global__ __launch_bounds__(224) void patch_rotate_kernel(
    const float* __restrict__ x,
    const void* __restrict__ mask_raw,
    float* __restrict__ out)
{
    // per-warp private regions: 7 warps x 2 patches x 80 float4 = 17.5 KB (reused per strip)
    __shared__ float4 tile[7 * 2 * PSTRIDE];

    const int bid = blockIdx.x;
    const int hp  = bid % (NP / 2);        // strip-pair index: strips 2hp, 2hp+1
    const int bc  = bid / (NP / 2);        // b*3 + c
    const int b   = bc / 3;
    const int t   = threadIdx.x;           // 0..223
    const int lane = t & 31;

    // thread -> (patch, 4x4 sub-block): 16 consecutive lanes own one patch
    const int wi = t >> 4;                 // 0..13 patch column
    const int p  = (t >> 4) & 1;           // patch slot within warp
    const int R  = (t >> 2) & 3;           // sub-block row group
    const int J  = t & 3;                  // sub-block fcol within patch
    const int fcol = 4 * wi + J;

    float4* wtile = tile + (t >> 5) * (2 * PSTRIDE);   // this warp's region

    const unsigned base4 = (unsigned)bc * (HW * HW / 4) + (unsigned)(2 * hp) * STRIP4;
    const float4* src4 = (const float4*)x + base4;
    float4*       dst4 = (float4*)out     + base4;

    // ---- front-batch ALL 8 independent LDG.128 (MLP_p1 = 8) ----
    float4 v[2][4];
    #pragma unroll
    for (int s = 0; s < 2; s++)
        #pragma unroll
        for (int k = 0; k < 4; k++)
            v[s][k] = src4[(unsigned)s * STRIP4 + (unsigned)(4*R + k) * S4 + fcol];

    // dtype probe: int32 bool -> every word 0/1; uint8 -> word>1 w.p. 7/8. P(miss)=8^-32.
    const unsigned pv = ((const unsigned int*)mask_raw)[lane];
    const int midx0 = b * (NP*NP) + wi * NP + 2*hp;                    // mask[b, wi, 2hp]
    const unsigned char m80 = ((const unsigned char*)mask_raw)[midx0];
    const unsigned char m81 = ((const unsigned char*)mask_raw)[midx0 + 1];

    const bool is_int32 = (__ballot_sync(0xFFFFFFFFu, pv > 1u) == 0u);
    bool mm[2];
    if (is_int32) {
        mm[0] = (((const int*)mask_raw)[midx0] != 0);      // predicated: no OOB if uint8
        mm[1] = (((const int*)mask_raw)[midx0 + 1] != 0);
    } else {
        mm[0] = (m80 != 0);
        mm[1] = (m81 != 0);
    }

    const int jbit = (J & 2);
    const int rbit = (R & 2);

    // ---- process the two strips back-to-back through the same warp-local smem ----
    #pragma unroll
    for (int s = 0; s < 2; s++) {
        if (mm[s]) {
            // register 4x4 transpose + swizzled vector STS
            // phys(row, fc) = row*5 + (fc ^ ((row>>2)&2))
            #pragma unroll
            for (int e = 0; e < 4; e++) {
                int row = 4*J + e;
                int adr = p * PSTRIDE + row * PROWS + (R ^ jbit);
                float4 w;
                w.x = (&v[s][0].x)[e]; w.y = (&v[s][1].x)[e];
                w.z = (&v[s][2].x)[e]; w.w = (&v[s][3].x)[e];
                wtile[adr] = w;
            }
        }
        __syncwarp();

        #pragma unroll
        for (int k = 0; k < 4; k++) {
            float4 o = v[s][k];
            if (mm[s]) {
                int row = 4*R + k;
                o = wtile[p * PSTRIDE + row * PROWS + (J ^ rbit)];
            }
            dst4[(unsigned)s * STRIP4 + (unsigned)(4*R + k) * S4 + fcol] = o;
        }
        __syncwarp();   // WAR: strip1's STS must not overwrite before strip0's LDS done
    }
}

extern "C" void kernel_launch(void* const* d_in, const int* in_sizes, int n_in,
                              void* d_out, int out_size)
{
    const float* x    = (const float*)d_in[0];
    const void*  mask = d_in[1];
    float*       out  = (float*)d_out;

    // one block per (b, c, strip-pair): 256*3*7 = 5376 blocks
    patch_rotate_kernel<<<5376, 224>>>(x, mask, out);
}